// round 5
// baseline (speedup 1.0000x reference)
#include <cuda_runtime.h>

#define SEQ   96
#define PRED  16
#define HID   64
#define FEAT  7
#define BPB   2               // batches per block
#define NBLK  256             // 512/2
#define NTHR  128
#define WIN   (SEQ + PRED)

typedef unsigned long long ull;

static __device__ __forceinline__ ull pack2(float a, float b){
    ull r; asm("mov.b64 %0, {%1, %2};" : "=l"(r) : "f"(a), "f"(b)); return r;
}
static __device__ __forceinline__ void unpack2(ull v, float &a, float &b){
    asm("mov.b64 {%0, %1}, %2;" : "=f"(a), "=f"(b) : "l"(v));
}
// d = a*b + d, packed f32x2 (Blackwell FFMA2), exact fp32 per lane
static __device__ __forceinline__ void ffma2(ull &d, ull a, ull b){
    asm("fma.rn.f32x2 %0, %1, %2, %0;" : "+l"(d) : "l"(a), "l"(b));
}
static __device__ __forceinline__ ull add2(ull a, ull b){
    ull r; asm("add.rn.f32x2 %0, %1, %2;" : "=l"(r) : "l"(a), "l"(b)); return r;
}

static __device__ __forceinline__ float sigmoid_fast(float x){
    float e = __expf(-x);
    return __fdividef(1.0f, 1.0f + e);
}
static __device__ __forceinline__ float tanhf_fast(float x){
    float e = __expf(-2.0f * x);
    return __fdividef(2.0f, 1.0f + e) - 1.0f;
}
// s=1 -> sigmoid, s=2 -> tanh
static __device__ __forceinline__ float act(float x, float s, float sm1){
    float e = __expf(-s * x);
    return __fdividef(s, 1.0f + e) - sm1;
}

__global__ void __launch_bounds__(NTHR, 2)
lstm_ar_kernel(const float* __restrict__ x,
               const float* __restrict__ W_ih,
               const float* __restrict__ W_hh,
               const float* __restrict__ b_ih,
               const float* __restrict__ b_hh,
               const float* __restrict__ fc_W,
               const float* __restrict__ fc_b,
               float* __restrict__ out)
{
    // sliding input window: [t][feat][b]
    __shared__ float sh_xw[WIN * FEAT * BPB];
    // hidden state, double-buffered: [buf][b][col]
    __shared__ float h_sh[2][BPB * HID];
    // i*g exchange: one float2 (b0,b1) per hidden unit
    __shared__ float2 sh_ig[HID];
    __shared__ float sh_fcW[FEAT * HID];
    __shared__ float sh_fcb[FEAT];

    const int tid = threadIdx.x;           // 0..127
    const int b0  = blockIdx.x * BPB;
    const int r0  = tid;                   // row A: gate 0 (i) or 1 (f)
    const int r1  = tid + 128;             // row B: gate 2 (g) or 3 (o)
    const bool hi = (tid >= 64);           // hi threads own (f,o) + cell state
    const int u   = tid & 63;              // hidden unit

    // ---------------- one-time init ----------------
    for (int i = tid; i < SEQ * FEAT * BPB; i += NTHR){
        int b = i & 1;
        int q = i >> 1;
        int f = q % FEAT;
        int t = q / FEAT;
        sh_xw[(t * FEAT + f) * BPB + b] =
            x[(size_t)(b0 + b) * SEQ * FEAT + t * FEAT + f];
    }
    for (int i = tid; i < FEAT * HID; i += NTHR) sh_fcW[i] = fc_W[i];
    if (tid < FEAT) sh_fcb[tid] = fc_b[tid];
    {
        float* hz = &h_sh[0][0];
        for (int i = tid; i < 2 * BPB * HID; i += NTHR) hz[i] = 0.0f;
    }

    // W_hh rows as natural column-pairs: whh*[c] = (W[2c], W[2c+1]) — 64 u64 regs
    ull whhA[HID / 2], whhB[HID / 2];
    {
        const ull* wa = reinterpret_cast<const ull*>(W_hh + (size_t)r0 * HID);
        const ull* wb = reinterpret_cast<const ull*>(W_hh + (size_t)r1 * HID);
        #pragma unroll
        for (int c = 0; c < HID / 2; c++){ whhA[c] = wa[c]; whhB[c] = wb[c]; }
    }
    // W_ih rows, splatted for batch-pair f32x2 accumulation
    ull wihA2[FEAT], wihB2[FEAT];
    #pragma unroll
    for (int f = 0; f < FEAT; f++){
        float wa = W_ih[r0 * FEAT + f];
        float wb = W_ih[r1 * FEAT + f];
        wihA2[f] = pack2(wa, wa);
        wihB2[f] = pack2(wb, wb);
    }
    const float biasA = b_ih[r0] + b_hh[r0];
    const float biasB = b_ih[r1] + b_hh[r1];
    const ull biasA2 = pack2(biasA, biasA);
    const ull biasB2 = pack2(biasB, biasB);

    // row A: always sigmoid; row B: tanh (lo: gate g) / sigmoid (hi: gate o)
    const float sB  = hi ? 1.0f : 2.0f;
    const float sBm = sB - 1.0f;

    float c0 = 0.0f, c1 = 0.0f;   // cell state (hi threads), per batch
    int p = 0;

    __syncthreads();

    // ---------------- 16 AR iterations x 96 recurrent steps ----------------
    for (int k = 0; k < PRED; k++){
        for (int t = 0; t < SEQ; t++){
            // ---- x-projection, packed over batches: lanes = (b0, b1) ----
            ull xA = biasA2, xB = biasB2;
            {
                const ull* xp =
                    reinterpret_cast<const ull*>(&sh_xw[(k + t) * FEAT * BPB]);
                #pragma unroll
                for (int f = 0; f < FEAT; f++){
                    ull xx = xp[f];              // (x_f[b0], x_f[b1])
                    ffma2(xA, xx, wihA2[f]);
                    ffma2(xB, xx, wihB2[f]);
                }
            }

            // ---- h-projection: 8 independent f32x2 chains ----
            ull aA0x = pack2(0.f, 0.f), aA0y = aA0x, aA1x = aA0x, aA1y = aA0x;
            ull aB0x = aA0x, aB0y = aA0x, aB1x = aA0x, aB1y = aA0x;
            const ulonglong2* h0 = reinterpret_cast<const ulonglong2*>(&h_sh[p][0]);
            const ulonglong2* h1 = reinterpret_cast<const ulonglong2*>(&h_sh[p][HID]);
            #pragma unroll
            for (int cc = 0; cc < HID / 8; cc++){
                ulonglong2 u0  = h0[2*cc];      // cols 8cc..8cc+3, batch 0
                ulonglong2 u0b = h0[2*cc+1];    // cols 8cc+4..8cc+7
                ulonglong2 u1  = h1[2*cc];      // batch 1
                ulonglong2 u1b = h1[2*cc+1];
                ffma2(aA0x, u0.x,  whhA[4*cc  ]);
                ffma2(aB0x, u0.x,  whhB[4*cc  ]);
                ffma2(aA1x, u1.x,  whhA[4*cc  ]);
                ffma2(aB1x, u1.x,  whhB[4*cc  ]);
                ffma2(aA0y, u0.y,  whhA[4*cc+1]);
                ffma2(aB0y, u0.y,  whhB[4*cc+1]);
                ffma2(aA1y, u1.y,  whhA[4*cc+1]);
                ffma2(aB1y, u1.y,  whhB[4*cc+1]);
                ffma2(aA0x, u0b.x, whhA[4*cc+2]);
                ffma2(aB0x, u0b.x, whhB[4*cc+2]);
                ffma2(aA1x, u1b.x, whhA[4*cc+2]);
                ffma2(aB1x, u1b.x, whhB[4*cc+2]);
                ffma2(aA0y, u0b.y, whhA[4*cc+3]);
                ffma2(aB0y, u0b.y, whhB[4*cc+3]);
                ffma2(aA1y, u1b.y, whhA[4*cc+3]);
                ffma2(aB1y, u1b.y, whhB[4*cc+3]);
            }
            // combine: packed tree-add, then horizontal
            ull sA0 = add2(aA0x, aA0y);
            ull sA1 = add2(aA1x, aA1y);
            ull sB0 = add2(aB0x, aB0y);
            ull sB1 = add2(aB1x, aB1y);
            float xa0, xa1, xb0, xb1, e, o;
            unpack2(xA, xa0, xa1);
            unpack2(xB, xb0, xb1);
            float vA0, vA1, vB0, vB1;
            unpack2(sA0, e, o); vA0 = (e + o) + xa0;
            unpack2(sA1, e, o); vA1 = (e + o) + xa1;
            unpack2(sB0, e, o); vB0 = (e + o) + xb0;
            unpack2(sB1, e, o); vB1 = (e + o) + xb1;

            // activations
            vA0 = sigmoid_fast(vA0);
            vA1 = sigmoid_fast(vA1);
            vB0 = act(vB0, sB, sBm);
            vB1 = act(vB1, sB, sBm);

            if (!hi){
                // lo: vA = i, vB = g  -> publish i*g
                sh_ig[u] = make_float2(vA0 * vB0, vA1 * vB1);
            }
            __syncthreads();
            if (hi){
                // hi: vA = f, vB = o; owns cell state of unit u
                float2 ig = sh_ig[u];
                c0 = fmaf(vA0, c0, ig.x);
                c1 = fmaf(vA1, c1, ig.y);
                h_sh[p ^ 1][      u] = vB0 * tanhf_fast(c0);
                h_sh[p ^ 1][HID + u] = vB1 * tanhf_fast(c1);
            }
            __syncthreads();
            p ^= 1;
        }

        // ---- fc head: pred = h @ fc_W^T + fc_b; append to window; emit ----
        if (tid < FEAT * BPB){
            int b = tid / FEAT;
            int o2 = tid - b * FEAT;
            float acc = sh_fcb[o2];
            #pragma unroll
            for (int jj = 0; jj < HID; jj++)
                acc += h_sh[p][b * HID + jj] * sh_fcW[o2 * HID + jj];
            out[(size_t)(b0 + b) * PRED * FEAT + k * FEAT + o2] = acc;
            sh_xw[((SEQ + k) * FEAT + o2) * BPB + b] = acc;
        }
        __syncthreads();
    }
}

extern "C" void kernel_launch(void* const* d_in, const int* in_sizes, int n_in,
                              void* d_out, int out_size)
{
    const float* x    = (const float*)d_in[0];
    const float* W_ih = (const float*)d_in[1];
    const float* W_hh = (const float*)d_in[2];
    const float* b_ih = (const float*)d_in[3];
    const float* b_hh = (const float*)d_in[4];
    const float* fc_W = (const float*)d_in[5];
    const float* fc_b = (const float*)d_in[6];
    float* out = (float*)d_out;

    lstm_ar_kernel<<<NBLK, NTHR>>>(x, W_ih, W_hh, b_ih, b_hh, fc_W, fc_b, out);
}